// round 12
// baseline (speedup 1.0000x reference)
#include <cuda_runtime.h>
#include <cuda_bf16.h>
#include <cstdint>

// ---------------------------------------------------------------------------
// C3 layer via split-bf16 tensor-core implicit GEMM.
//   Pass 1: split x (fp32) into bf16 hi + bf16 lo residual arrays.
//   Pass 2: build pre-swizzled per-lane weight B-fragments (hi/lo).
//   Pass 3: conv = 5 kx-shifted GEMMs, K=(c,ky)=30 taps (pad 32),
//           mma.sync.m16n8k16 bf16: D(16px x 16oc) per warp,
//           3-term split product: xhi*whi + xhi*wlo + xlo*whi.
// ---------------------------------------------------------------------------

#define XN (128*6*256*256)

__device__ __nv_bfloat16 g_xhi[XN];
__device__ __nv_bfloat16 g_xlo[XN];
__device__ uint32_t g_wfrag[5*2*2*32*4];   // [kx][kh][nh][lane][4: bhi0,bhi1,blo0,blo1]

__device__ constexpr int POC[6][10] = {
    {0, 4, 5, 6,  9, 10, 11, 12, 14, 15},
    {0, 1, 5, 6,  7, 10, 11, 12, 13, 15},
    {0, 1, 2, 6,  7,  8, 11, 13, 14, 15},
    {1, 2, 3, 6,  7,  8,  9, 12, 14, 15},
    {2, 3, 4, 7,  8,  9, 10, 12, 13, 15},
    {3, 4, 5, 8,  9, 10, 11, 13, 14, 15}
};
__device__ constexpr int POFF[6][10] = {
    {  0, 300, 375, 450, 750,  850,  950, 1050, 1250, 1350},
    { 25,  75, 400, 475, 550,  875,  975, 1075, 1150, 1375},
    { 50, 100, 150, 500, 575,  650, 1000, 1175, 1275, 1400},
    {125, 175, 225, 525, 600,  675,  775, 1100, 1300, 1425},
    {200, 250, 325, 625, 700,  800,  900, 1125, 1200, 1450},
    {275, 350, 425, 725, 825,  925, 1025, 1225, 1325, 1475}
};

// ---------------- Pass 1: fp32 -> bf16 hi/lo split ----------------
__global__ __launch_bounds__(256) void split_kernel(const float* __restrict__ x)
{
    int i = blockIdx.x * 256 + threadIdx.x;      // float4 index, XN/4 total
    float4 v = ((const float4*)x)[i];
    __nv_bfloat16 h0 = __float2bfloat16(v.x);
    __nv_bfloat16 h1 = __float2bfloat16(v.y);
    __nv_bfloat16 h2 = __float2bfloat16(v.z);
    __nv_bfloat16 h3 = __float2bfloat16(v.w);
    __nv_bfloat16 l0 = __float2bfloat16(v.x - __bfloat162float(h0));
    __nv_bfloat16 l1 = __float2bfloat16(v.y - __bfloat162float(h1));
    __nv_bfloat16 l2 = __float2bfloat16(v.z - __bfloat162float(h2));
    __nv_bfloat16 l3 = __float2bfloat16(v.w - __bfloat162float(h3));
    uint2 ph, pl;
    ph.x = (uint32_t)__bfloat16_as_ushort(h0) | ((uint32_t)__bfloat16_as_ushort(h1) << 16);
    ph.y = (uint32_t)__bfloat16_as_ushort(h2) | ((uint32_t)__bfloat16_as_ushort(h3) << 16);
    pl.x = (uint32_t)__bfloat16_as_ushort(l0) | ((uint32_t)__bfloat16_as_ushort(l1) << 16);
    pl.y = (uint32_t)__bfloat16_as_ushort(l2) | ((uint32_t)__bfloat16_as_ushort(l3) << 16);
    ((uint2*)g_xhi)[i] = ph;
    ((uint2*)g_xlo)[i] = pl;
}

// ---------------- Pass 2: weight B-fragments ----------------
__device__ __forceinline__ float wlookup(const float* w3, const float* w4,
                                         const float* w6, int oc, int tap, int kx)
{
    if (tap >= 30) return 0.0f;
    int c  = tap / 5;
    int ky = tap % 5;
    int base = -1;
    for (int j = 0; j < 10; ++j)
        if (POC[c][j] == oc) { base = POFF[c][j]; break; }
    if (base < 0) return 0.0f;
    int off = base + ky * 5 + kx;
    return (off < 450) ? w3[off] : (off < 1350) ? w4[off - 450] : w6[off - 1350];
}

__global__ void wfrag_kernel(const float* __restrict__ w3,
                             const float* __restrict__ w4,
                             const float* __restrict__ w6)
{
    int idx = blockIdx.x * 128 + threadIdx.x;   // 0..639
    if (idx >= 640) return;
    int t  = idx & 31;
    int nh = (idx >> 5) & 1;
    int kh = (idx >> 6) & 1;
    int kx = idx >> 7;
    int j = t & 3, n = t >> 2;
    int oc = nh * 8 + n;

    // b-frag elements: klocal = {2j, 2j+1, 2j+8, 2j+9}, tap = kh*16 + klocal
    float w0 = wlookup(w3, w4, w6, oc, kh*16 + 2*j,     kx);
    float w1 = wlookup(w3, w4, w6, oc, kh*16 + 2*j + 1, kx);
    float w2 = wlookup(w3, w4, w6, oc, kh*16 + 2*j + 8, kx);
    float w3v= wlookup(w3, w4, w6, oc, kh*16 + 2*j + 9, kx);

    __nv_bfloat16 h; uint32_t hi0, hi1, lo0, lo1; uint32_t u;
    h = __float2bfloat16(w0); hi0 = __bfloat16_as_ushort(h);
    u = __bfloat16_as_ushort(__float2bfloat16(w0 - __bfloat162float(h))); lo0 = u;
    h = __float2bfloat16(w1); hi0 |= (uint32_t)__bfloat16_as_ushort(h) << 16;
    u = __bfloat16_as_ushort(__float2bfloat16(w1 - __bfloat162float(h))); lo0 |= u << 16;
    h = __float2bfloat16(w2); hi1 = __bfloat16_as_ushort(h);
    u = __bfloat16_as_ushort(__float2bfloat16(w2 - __bfloat162float(h))); lo1 = u;
    h = __float2bfloat16(w3v); hi1 |= (uint32_t)__bfloat16_as_ushort(h) << 16;
    u = __bfloat16_as_ushort(__float2bfloat16(w3v - __bfloat162float(h))); lo1 |= u << 16;

    uint32_t* dst = g_wfrag + (size_t)idx * 4;
    dst[0] = hi0; dst[1] = hi1; dst[2] = lo0; dst[3] = lo1;
}

// ---------------- Pass 3: main conv ----------------
#define MMA(d, a0,a1,a2,a3, b0,b1)                                             \
    asm volatile("mma.sync.aligned.m16n8k16.row.col.f32.bf16.bf16.f32 "        \
                 "{%0,%1,%2,%3}, {%4,%5,%6,%7}, {%8,%9}, {%0,%1,%2,%3};"       \
                 : "+f"(d[0]), "+f"(d[1]), "+f"(d[2]), "+f"(d[3])              \
                 : "r"(a0), "r"(a1), "r"(a2), "r"(a3), "r"(b0), "r"(b1))

__global__ __launch_bounds__(256) void conv_mma_kernel(
    const float* __restrict__ b3, const float* __restrict__ b4,
    const float* __restrict__ b6, float* __restrict__ out)
{
    // xs[hi/lo]: 132 columns (pixel positions), each 20 u32 = 40 bf16 slots
    // (k taps 0..31 used; u32 slot 15 = taps 30,31 zeroed). Stride 20 u32
    // makes A-fragment LDS.32 bank-conflict-free (20m+j distinct mod 32).
    __shared__ uint32_t xs[2][132 * 20];
    __shared__ uint4 wsm[640];
    __shared__ float bsm[16];

    const int tid = threadIdx.x;
    const int b = blockIdx.z, p = blockIdx.y;
    const int Q0 = blockIdx.x ? 124 : 0;

    for (int i = tid; i < 640; i += 256) wsm[i] = ((const uint4*)g_wfrag)[i];
    if (tid < 16)
        bsm[tid] = (tid < 6) ? b3[tid] : (tid < 15) ? b4[tid - 6] : b6[0];
    for (int i = tid; i < 132; i += 256) {
        xs[0][i * 20 + 15] = 0;
        xs[1][i * 20 + 15] = 0;
    }

    // Stage 30 tap-rows x 132 cols into column-major (taps contiguous) tiles.
    unsigned short* xh = (unsigned short*)xs[0];
    unsigned short* xl = (unsigned short*)xs[1];
    for (int i = tid; i < 990; i += 256) {
        int row = i / 33, seg = i % 33;          // row = tap (c,ky)
        int c = row / 5, ky = row % 5;
        size_t g = (((size_t)(b * 6 + c)) * 256 + (p + ky)) * 256 + Q0 + seg * 4;
        uint2 vh = *(const uint2*)(g_xhi + g);
        uint2 vl = *(const uint2*)(g_xlo + g);
        int col = seg * 4;
        xh[(col + 0) * 40 + row] = (unsigned short)(vh.x);
        xh[(col + 1) * 40 + row] = (unsigned short)(vh.x >> 16);
        xh[(col + 2) * 40 + row] = (unsigned short)(vh.y);
        xh[(col + 3) * 40 + row] = (unsigned short)(vh.y >> 16);
        xl[(col + 0) * 40 + row] = (unsigned short)(vl.x);
        xl[(col + 1) * 40 + row] = (unsigned short)(vl.x >> 16);
        xl[(col + 2) * 40 + row] = (unsigned short)(vl.y);
        xl[(col + 3) * 40 + row] = (unsigned short)(vl.y >> 16);
    }
    __syncthreads();

    const int w = tid >> 5, t = tid & 31;
    const int j = t & 3, m = t >> 2;

    float d0[4], d1[4];
    {
        int oc0 = 2 * j;
        d0[0] = bsm[oc0];     d0[1] = bsm[oc0 + 1];
        d0[2] = d0[0];        d0[3] = d0[1];
        d1[0] = bsm[8 + oc0]; d1[1] = bsm[8 + oc0 + 1];
        d1[2] = d1[0];        d1[3] = d1[1];
    }

    const uint32_t* xhu = xs[0];
    const uint32_t* xlu = xs[1];
    const int abase = (16 * w + m) * 20 + j;   // u32 index; colB = +160; khi = +4

    #pragma unroll
    for (int kx = 0; kx < 5; ++kx) {
        #pragma unroll
        for (int kh = 0; kh < 2; ++kh) {
            const int o = abase + kx * 20 + kh * 8;
            uint32_t ah0 = xhu[o],       ah1 = xhu[o + 160];
            uint32_t ah2 = xhu[o + 4],   ah3 = xhu[o + 164];
            uint32_t al0 = xlu[o],       al1 = xlu[o + 160];
            uint32_t al2 = xlu[o + 4],   al3 = xlu[o + 164];

            uint4 B0 = wsm[((kx * 2 + kh) * 2 + 0) * 32 + t];
            uint4 B1 = wsm[((kx * 2 + kh) * 2 + 1) * 32 + t];

            MMA(d0, ah0, ah1, ah2, ah3, B0.x, B0.y);   // xhi * whi
            MMA(d0, ah0, ah1, ah2, ah3, B0.z, B0.w);   // xhi * wlo
            MMA(d0, al0, al1, al2, al3, B0.x, B0.y);   // xlo * whi
            MMA(d1, ah0, ah1, ah2, ah3, B1.x, B1.y);
            MMA(d1, ah0, ah1, ah2, ah3, B1.z, B1.w);
            MMA(d1, al0, al1, al2, al3, B1.x, B1.y);
        }
    }

    // Epilogue: D frag (m16n8): d[0]:(m, oc0) d[1]:(m, oc0+1) d[2]:(m+8,...)
    const int q = Q0 + 16 * w + m;
    const int oc0 = 2 * j;
    {
        float* o = out + (((size_t)b * 16 + oc0) * 252 + p) * 252 + q;
        o[0] = d0[0];  o[8] = d0[2];
        o += 252 * 252;
        o[0] = d0[1];  o[8] = d0[3];
        o = out + (((size_t)b * 16 + 8 + oc0) * 252 + p) * 252 + q;
        o[0] = d1[0];  o[8] = d1[2];
        o += 252 * 252;
        o[0] = d1[1];  o[8] = d1[3];
    }
}

extern "C" void kernel_launch(void* const* d_in, const int* in_sizes, int n_in,
                              void* d_out, int out_size)
{
    const float* x  = (const float*)d_in[0];
    const float* w3 = (const float*)d_in[1];
    const float* b3 = (const float*)d_in[2];
    const float* w4 = (const float*)d_in[3];
    const float* b4 = (const float*)d_in[4];
    const float* w6 = (const float*)d_in[5];
    const float* b6 = (const float*)d_in[6];
    float* out = (float*)d_out;

    split_kernel<<<XN / 4 / 256, 256>>>(x);
    wfrag_kernel<<<5, 128>>>(w3, w4, w6);
    conv_mma_kernel<<<dim3(2, 252, 128), 256>>>(b3, b4, b6, out);
}

// round 13
// speedup vs baseline: 1.9022x; 1.9022x over previous
#include <cuda_runtime.h>
#include <cuda_bf16.h>
#include <cstdint>

// ---------------------------------------------------------------------------
// C3 layer via split-bf16 tensor-core implicit GEMM (warp mma.sync).
//   wfrag: pre-swizzled per-lane weight B-fragments (hi/lo bf16 split).
//   split: x fp32 -> bf16 hi + lo residual.
//   conv:  5 kx-shifted GEMMs, K=30 taps (pad 32), m16n8k16 bf16,
//          3-term split product. Smem x-tile stored as u32 tap-pairs,
//          [col][tp] stride 23 u32 (odd -> conflict-free staging stores,
//          near-conflict-free A loads). 4 accumulator chains per warp
//          (2 m-tiles x 2 oc-halves) to cover HMMA latency.
// ---------------------------------------------------------------------------

#define XN (128*6*256*256)

__device__ __nv_bfloat16 g_xhi[XN];
__device__ __nv_bfloat16 g_xlo[XN];
__device__ uint32_t g_wfrag[5*2*2*32*4];   // [kx][kh][nh][lane][4: bhi0,bhi1,blo0,blo1]

__device__ constexpr int POC[6][10] = {
    {0, 4, 5, 6,  9, 10, 11, 12, 14, 15},
    {0, 1, 5, 6,  7, 10, 11, 12, 13, 15},
    {0, 1, 2, 6,  7,  8, 11, 13, 14, 15},
    {1, 2, 3, 6,  7,  8,  9, 12, 14, 15},
    {2, 3, 4, 7,  8,  9, 10, 12, 13, 15},
    {3, 4, 5, 8,  9, 10, 11, 13, 14, 15}
};
__device__ constexpr int POFF[6][10] = {
    {  0, 300, 375, 450, 750,  850,  950, 1050, 1250, 1350},
    { 25,  75, 400, 475, 550,  875,  975, 1075, 1150, 1375},
    { 50, 100, 150, 500, 575,  650, 1000, 1175, 1275, 1400},
    {125, 175, 225, 525, 600,  675,  775, 1100, 1300, 1425},
    {200, 250, 325, 625, 700,  800,  900, 1125, 1200, 1450},
    {275, 350, 425, 725, 825,  925, 1025, 1225, 1325, 1475}
};

// ---------------- split: fp32 -> bf16 hi/lo ----------------
__global__ __launch_bounds__(256) void split_kernel(const float* __restrict__ x)
{
    int i = blockIdx.x * 256 + threadIdx.x;
    float4 v = ((const float4*)x)[i];
    __nv_bfloat16 h0 = __float2bfloat16(v.x);
    __nv_bfloat16 h1 = __float2bfloat16(v.y);
    __nv_bfloat16 h2 = __float2bfloat16(v.z);
    __nv_bfloat16 h3 = __float2bfloat16(v.w);
    __nv_bfloat16 l0 = __float2bfloat16(v.x - __bfloat162float(h0));
    __nv_bfloat16 l1 = __float2bfloat16(v.y - __bfloat162float(h1));
    __nv_bfloat16 l2 = __float2bfloat16(v.z - __bfloat162float(h2));
    __nv_bfloat16 l3 = __float2bfloat16(v.w - __bfloat162float(h3));
    uint2 ph, pl;
    ph.x = (uint32_t)__bfloat16_as_ushort(h0) | ((uint32_t)__bfloat16_as_ushort(h1) << 16);
    ph.y = (uint32_t)__bfloat16_as_ushort(h2) | ((uint32_t)__bfloat16_as_ushort(h3) << 16);
    pl.x = (uint32_t)__bfloat16_as_ushort(l0) | ((uint32_t)__bfloat16_as_ushort(l1) << 16);
    pl.y = (uint32_t)__bfloat16_as_ushort(l2) | ((uint32_t)__bfloat16_as_ushort(l3) << 16);
    ((uint2*)g_xhi)[i] = ph;
    ((uint2*)g_xlo)[i] = pl;
}

// ---------------- wfrag ----------------
__device__ __forceinline__ float wlookup(const float* w3, const float* w4,
                                         const float* w6, int oc, int tap, int kx)
{
    if (tap >= 30) return 0.0f;
    int c  = tap / 5;
    int ky = tap % 5;
    int base = -1;
    for (int j = 0; j < 10; ++j)
        if (POC[c][j] == oc) { base = POFF[c][j]; break; }
    if (base < 0) return 0.0f;
    int off = base + ky * 5 + kx;
    return (off < 450) ? w3[off] : (off < 1350) ? w4[off - 450] : w6[off - 1350];
}

__global__ void wfrag_kernel(const float* __restrict__ w3,
                             const float* __restrict__ w4,
                             const float* __restrict__ w6)
{
    int idx = blockIdx.x * 128 + threadIdx.x;   // 0..639
    if (idx >= 640) return;
    int t  = idx & 31;
    int nh = (idx >> 5) & 1;
    int kh = (idx >> 6) & 1;
    int kx = idx >> 7;
    int j = t & 3, n = t >> 2;
    int oc = nh * 8 + n;

    float w0 = wlookup(w3, w4, w6, oc, kh*16 + 2*j,     kx);
    float w1 = wlookup(w3, w4, w6, oc, kh*16 + 2*j + 1, kx);
    float w2 = wlookup(w3, w4, w6, oc, kh*16 + 2*j + 8, kx);
    float w3v= wlookup(w3, w4, w6, oc, kh*16 + 2*j + 9, kx);

    __nv_bfloat16 h; uint32_t hi0, hi1, lo0, lo1; uint32_t u;
    h = __float2bfloat16(w0); hi0 = __bfloat16_as_ushort(h);
    u = __bfloat16_as_ushort(__float2bfloat16(w0 - __bfloat162float(h))); lo0 = u;
    h = __float2bfloat16(w1); hi0 |= (uint32_t)__bfloat16_as_ushort(h) << 16;
    u = __bfloat16_as_ushort(__float2bfloat16(w1 - __bfloat162float(h))); lo0 |= u << 16;
    h = __float2bfloat16(w2); hi1 = __bfloat16_as_ushort(h);
    u = __bfloat16_as_ushort(__float2bfloat16(w2 - __bfloat162float(h))); lo1 = u;
    h = __float2bfloat16(w3v); hi1 |= (uint32_t)__bfloat16_as_ushort(h) << 16;
    u = __bfloat16_as_ushort(__float2bfloat16(w3v - __bfloat162float(h))); lo1 |= u << 16;

    uint32_t* dst = g_wfrag + (size_t)idx * 4;
    dst[0] = hi0; dst[1] = hi1; dst[2] = lo0; dst[3] = lo1;
}

// ---------------- conv ----------------
#define MMA(d, a0,a1,a2,a3, b0,b1)                                             \
    asm volatile("mma.sync.aligned.m16n8k16.row.col.f32.bf16.bf16.f32 "        \
                 "{%0,%1,%2,%3}, {%4,%5,%6,%7}, {%8,%9}, {%0,%1,%2,%3};"       \
                 : "+f"(d[0]), "+f"(d[1]), "+f"(d[2]), "+f"(d[3])              \
                 : "r"(a0), "r"(a1), "r"(a2), "r"(a3), "r"(b0), "r"(b1))

#define XSTRIDE 23   // u32 stride per column (odd -> conflict-free staging)

__global__ __launch_bounds__(128) void conv_mma_kernel(
    const float* __restrict__ b3, const float* __restrict__ b4,
    const float* __restrict__ b6, float* __restrict__ out)
{
    // xs: 132 cols x 16 tap-pair u32 (tp 0..14 data, 15 zero), stride 23.
    __shared__ uint32_t xs[2][132 * XSTRIDE];
    __shared__ uint4 wsm[640];
    __shared__ float bsm[16];

    const int tid = threadIdx.x;
    const int b = blockIdx.z, p = blockIdx.y;
    const int Q0 = blockIdx.x ? 124 : 0;

    for (int i = tid; i < 640; i += 128) wsm[i] = ((const uint4*)g_wfrag)[i];
    if (tid < 16)
        bsm[tid] = (tid < 6) ? b3[tid] : (tid < 15) ? b4[tid - 6] : b6[0];
    for (int i = tid; i < 132; i += 128) {
        xs[0][i * XSTRIDE + 15] = 0;
        xs[1][i * XSTRIDE + 15] = 0;
    }

    // Stage: i = (tap-pair tp, 4-col segment seg). Coalesced uint2 row
    // loads, __byte_perm merges -> STS.32 at odd stride (conflict-free).
    for (int i = tid; i < 495; i += 128) {
        int tp = i / 33, seg = i % 33;
        int t0 = 2 * tp, t1 = t0 + 1;
        int c0 = t0 / 5, ky0 = t0 % 5;
        int c1 = t1 / 5, ky1 = t1 % 5;
        size_t g0 = (((size_t)(b * 6 + c0)) * 256 + (p + ky0)) * 256 + Q0 + seg * 4;
        size_t g1 = (((size_t)(b * 6 + c1)) * 256 + (p + ky1)) * 256 + Q0 + seg * 4;
        uint2 h0 = *(const uint2*)(g_xhi + g0);
        uint2 h1 = *(const uint2*)(g_xhi + g1);
        uint2 l0 = *(const uint2*)(g_xlo + g0);
        uint2 l1 = *(const uint2*)(g_xlo + g1);
        int base = (seg * 4) * XSTRIDE + tp;
        xs[0][base]               = __byte_perm(h0.x, h1.x, 0x5410);
        xs[0][base + XSTRIDE]     = __byte_perm(h0.x, h1.x, 0x7632);
        xs[0][base + 2 * XSTRIDE] = __byte_perm(h0.y, h1.y, 0x5410);
        xs[0][base + 3 * XSTRIDE] = __byte_perm(h0.y, h1.y, 0x7632);
        xs[1][base]               = __byte_perm(l0.x, l1.x, 0x5410);
        xs[1][base + XSTRIDE]     = __byte_perm(l0.x, l1.x, 0x7632);
        xs[1][base + 2 * XSTRIDE] = __byte_perm(l0.y, l1.y, 0x5410);
        xs[1][base + 3 * XSTRIDE] = __byte_perm(l0.y, l1.y, 0x7632);
    }
    __syncthreads();

    const int w = tid >> 5, t = tid & 31;
    const int j = t & 3, m = t >> 2;

    float d00[4], d01[4], d10[4], d11[4];
    {
        int oc0 = 2 * j;
        d00[0] = bsm[oc0];     d00[1] = bsm[oc0 + 1];  d00[2] = d00[0]; d00[3] = d00[1];
        d01[0] = bsm[8 + oc0]; d01[1] = bsm[9 + oc0];  d01[2] = d01[0]; d01[3] = d01[1];
        d10[0] = d00[0]; d10[1] = d00[1]; d10[2] = d00[0]; d10[3] = d00[1];
        d11[0] = d01[0]; d11[1] = d01[1]; d11[2] = d01[0]; d11[3] = d01[1];
    }

    const uint32_t* xh = xs[0];
    const uint32_t* xl = xs[1];
    const int ab0 = (32 * w + m) * XSTRIDE + j;        // m-tile 0
    const int ab1 = (32 * w + 16 + m) * XSTRIDE + j;   // m-tile 1
    const int CB = 8 * XSTRIDE;                        // +8 cols (a1/a3 rows)

    #pragma unroll
    for (int kx = 0; kx < 5; ++kx) {
        #pragma unroll
        for (int kh = 0; kh < 2; ++kh) {
            const int o0 = ab0 + kx * XSTRIDE + kh * 8;
            const int o1 = ab1 + kx * XSTRIDE + kh * 8;

            uint32_t p0h0 = xh[o0],      p0h1 = xh[o0 + CB];
            uint32_t p0h2 = xh[o0 + 4],  p0h3 = xh[o0 + CB + 4];
            uint32_t p1h0 = xh[o1],      p1h1 = xh[o1 + CB];
            uint32_t p1h2 = xh[o1 + 4],  p1h3 = xh[o1 + CB + 4];
            uint32_t p0l0 = xl[o0],      p0l1 = xl[o0 + CB];
            uint32_t p0l2 = xl[o0 + 4],  p0l3 = xl[o0 + CB + 4];
            uint32_t p1l0 = xl[o1],      p1l1 = xl[o1 + CB];
            uint32_t p1l2 = xl[o1 + 4],  p1l3 = xl[o1 + CB + 4];

            uint4 B0 = wsm[((kx * 2 + kh) * 2 + 0) * 32 + t];
            uint4 B1 = wsm[((kx * 2 + kh) * 2 + 1) * 32 + t];

            // 12 MMAs, 4 independent chains, reuse distance 4.
            MMA(d00, p0h0, p0h1, p0h2, p0h3, B0.x, B0.y);
            MMA(d10, p1h0, p1h1, p1h2, p1h3, B0.x, B0.y);
            MMA(d01, p0h0, p0h1, p0h2, p0h3, B1.x, B1.y);
            MMA(d11, p1h0, p1h1, p1h2, p1h3, B1.x, B1.y);
            MMA(d00, p0h0, p0h1, p0h2, p0h3, B0.z, B0.w);
            MMA(d10, p1h0, p1h1, p1h2, p1h3, B0.z, B0.w);
            MMA(d01, p0h0, p0h1, p0h2, p0h3, B1.z, B1.w);
            MMA(d11, p1h0, p1h1, p1h2, p1h3, B1.z, B1.w);
            MMA(d00, p0l0, p0l1, p0l2, p0l3, B0.x, B0.y);
            MMA(d10, p1l0, p1l1, p1l2, p1l3, B0.x, B0.y);
            MMA(d01, p0l0, p0l1, p0l2, p0l3, B1.x, B1.y);
            MMA(d11, p1l0, p1l1, p1l2, p1l3, B1.x, B1.y);
        }
    }

    // Epilogue.
    const int oc0 = 2 * j;
    #pragma unroll
    for (int mt = 0; mt < 2; ++mt) {
        const int q = Q0 + 32 * w + 16 * mt + m;
        float* da = mt ? d10 : d00;
        float* db = mt ? d11 : d01;
        float* o = out + (((size_t)b * 16 + oc0) * 252 + p) * 252 + q;
        o[0] = da[0];  o[8] = da[2];
        o += 252 * 252;
        o[0] = da[1];  o[8] = da[3];
        o = out + (((size_t)b * 16 + 8 + oc0) * 252 + p) * 252 + q;
        o[0] = db[0];  o[8] = db[2];
        o += 252 * 252;
        o[0] = db[1];  o[8] = db[3];
    }
}

extern "C" void kernel_launch(void* const* d_in, const int* in_sizes, int n_in,
                              void* d_out, int out_size)
{
    const float* x  = (const float*)d_in[0];
    const float* w3 = (const float*)d_in[1];
    const float* b3 = (const float*)d_in[2];
    const float* w4 = (const float*)d_in[3];
    const float* b4 = (const float*)d_in[4];
    const float* w6 = (const float*)d_in[5];
    const float* b6 = (const float*)d_in[6];
    float* out = (float*)d_out;

    wfrag_kernel<<<5, 128>>>(w3, w4, w6);
    split_kernel<<<XN / 4 / 256, 256>>>(x);
    conv_mma_kernel<<<dim3(2, 252, 128), 128>>>(b3, b4, b6, out);
}

// round 14
// speedup vs baseline: 3.3987x; 1.7867x over previous
#include <cuda_runtime.h>
#include <cuda_fp16.h>
#include <cstdint>

// ---------------------------------------------------------------------------
// C3 layer via single-term fp16 tensor-core implicit GEMM (mma.sync).
//   wfrag: pre-swizzled per-lane fp16 weight B-fragments.
//   conv:  5 kx-shifted GEMMs, K=30 (c,ky) taps (pad 32), m16n8k16
//          f32.f16.f16.f32. x converted fp32->fp16 during smem staging
//          (no separate split pass, no extra global arrays).
//   fp16 (11-bit mantissa) + fp32 accumulate: rel_err ~ 2^-11 ~ 3e-4 < 1e-3.
//   Smem x-tile: u32 tap-pairs [col][tp], stride 23 (odd -> conflict-free
//   staging stores). 4 independent MMA chains per warp.
// ---------------------------------------------------------------------------

__device__ uint2 g_wfrag[5*2*2*32];   // [kx][kh][nh][lane] = (b0, b1)

__device__ constexpr int POC[6][10] = {
    {0, 4, 5, 6,  9, 10, 11, 12, 14, 15},
    {0, 1, 5, 6,  7, 10, 11, 12, 13, 15},
    {0, 1, 2, 6,  7,  8, 11, 13, 14, 15},
    {1, 2, 3, 6,  7,  8,  9, 12, 14, 15},
    {2, 3, 4, 7,  8,  9, 10, 12, 13, 15},
    {3, 4, 5, 8,  9, 10, 11, 13, 14, 15}
};
__device__ constexpr int POFF[6][10] = {
    {  0, 300, 375, 450, 750,  850,  950, 1050, 1250, 1350},
    { 25,  75, 400, 475, 550,  875,  975, 1075, 1150, 1375},
    { 50, 100, 150, 500, 575,  650, 1000, 1175, 1275, 1400},
    {125, 175, 225, 525, 600,  675,  775, 1100, 1300, 1425},
    {200, 250, 325, 625, 700,  800,  900, 1125, 1200, 1450},
    {275, 350, 425, 725, 825,  925, 1025, 1225, 1325, 1475}
};

__device__ __forceinline__ uint32_t packh2(float lo, float hi) {
    __half2 h = __floats2half2_rn(lo, hi);   // lo -> low 16 bits
    uint32_t u;
    asm("mov.b32 %0, %1;" : "=r"(u) : "r"(*(uint32_t*)&h));
    return u;
}

// ---------------- wfrag ----------------
__device__ __forceinline__ float wlookup(const float* w3, const float* w4,
                                         const float* w6, int oc, int tap, int kx)
{
    if (tap >= 30) return 0.0f;
    int c  = tap / 5;
    int ky = tap % 5;
    int base = -1;
    for (int j = 0; j < 10; ++j)
        if (POC[c][j] == oc) { base = POFF[c][j]; break; }
    if (base < 0) return 0.0f;
    int off = base + ky * 5 + kx;
    return (off < 450) ? w3[off] : (off < 1350) ? w4[off - 450] : w6[off - 1350];
}

__global__ void wfrag_kernel(const float* __restrict__ w3,
                             const float* __restrict__ w4,
                             const float* __restrict__ w6)
{
    int idx = blockIdx.x * 128 + threadIdx.x;   // 0..639
    if (idx >= 640) return;
    int t  = idx & 31;
    int nh = (idx >> 5) & 1;
    int kh = (idx >> 6) & 1;
    int kx = idx >> 7;
    int j = t & 3, n = t >> 2;
    int oc = nh * 8 + n;

    // b-frag: b0 = taps (kh*16 + 2j, +1), b1 = taps (kh*16 + 2j+8, +9)
    float w0 = wlookup(w3, w4, w6, oc, kh*16 + 2*j,     kx);
    float w1 = wlookup(w3, w4, w6, oc, kh*16 + 2*j + 1, kx);
    float w2 = wlookup(w3, w4, w6, oc, kh*16 + 2*j + 8, kx);
    float w3v= wlookup(w3, w4, w6, oc, kh*16 + 2*j + 9, kx);

    uint2 d;
    d.x = packh2(w0, w1);
    d.y = packh2(w2, w3v);
    g_wfrag[idx] = d;
}

// ---------------- conv ----------------
#define MMA(d, a0,a1,a2,a3, b0,b1)                                             \
    asm volatile("mma.sync.aligned.m16n8k16.row.col.f32.f16.f16.f32 "          \
                 "{%0,%1,%2,%3}, {%4,%5,%6,%7}, {%8,%9}, {%0,%1,%2,%3};"       \
                 : "+f"(d[0]), "+f"(d[1]), "+f"(d[2]), "+f"(d[3])              \
                 : "r"(a0), "r"(a1), "r"(a2), "r"(a3), "r"(b0), "r"(b1))

#define XSTRIDE 23   // u32 stride per column (odd -> conflict-free staging)

__global__ __launch_bounds__(128) void conv_mma_kernel(
    const float* __restrict__ x,
    const float* __restrict__ b3, const float* __restrict__ b4,
    const float* __restrict__ b6, float* __restrict__ out)
{
    // xs: 132 cols x 16 tap-pair u32 (tp 0..14 data, 15 zero), stride 23.
    __shared__ uint32_t xs[132 * XSTRIDE];
    __shared__ uint2 wsm[640];
    __shared__ float bsm[16];

    const int tid = threadIdx.x;
    const int b = blockIdx.z, p = blockIdx.y;
    const int Q0 = blockIdx.x ? 124 : 0;

    for (int i = tid; i < 640; i += 128) wsm[i] = g_wfrag[i];
    if (tid < 16)
        bsm[tid] = (tid < 6) ? b3[tid] : (tid < 15) ? b4[tid - 6] : b6[0];
    for (int i = tid; i < 132; i += 128)
        xs[i * XSTRIDE + 15] = 0;

    // Stage: i = (tap-pair tp, 4-col segment seg). Coalesced float4 row
    // loads, fp32->fp16 convert, STS.32 at odd stride (conflict-free).
    for (int i = tid; i < 495; i += 128) {
        int tp = i / 33, seg = i % 33;
        int t0 = 2 * tp, t1 = t0 + 1;
        int c0 = t0 / 5, ky0 = t0 % 5;
        int c1 = t1 / 5, ky1 = t1 % 5;
        float4 f0 = *(const float4*)(x + (((size_t)(b * 6 + c0)) * 256 + (p + ky0)) * 256 + Q0 + seg * 4);
        float4 f1 = *(const float4*)(x + (((size_t)(b * 6 + c1)) * 256 + (p + ky1)) * 256 + Q0 + seg * 4);
        int base = (seg * 4) * XSTRIDE + tp;
        xs[base]               = packh2(f0.x, f1.x);
        xs[base + XSTRIDE]     = packh2(f0.y, f1.y);
        xs[base + 2 * XSTRIDE] = packh2(f0.z, f1.z);
        xs[base + 3 * XSTRIDE] = packh2(f0.w, f1.w);
    }
    __syncthreads();

    const int w = tid >> 5, t = tid & 31;
    const int j = t & 3, m = t >> 2;

    float d00[4], d01[4], d10[4], d11[4];
    {
        int oc0 = 2 * j;
        d00[0] = bsm[oc0];     d00[1] = bsm[oc0 + 1];  d00[2] = d00[0]; d00[3] = d00[1];
        d01[0] = bsm[8 + oc0]; d01[1] = bsm[9 + oc0];  d01[2] = d01[0]; d01[3] = d01[1];
        d10[0] = d00[0]; d10[1] = d00[1]; d10[2] = d00[0]; d10[3] = d00[1];
        d11[0] = d01[0]; d11[1] = d01[1]; d11[2] = d01[0]; d11[3] = d01[1];
    }

    const int ab0 = (32 * w + m) * XSTRIDE + j;        // m-tile 0
    const int ab1 = (32 * w + 16 + m) * XSTRIDE + j;   // m-tile 1
    const int CB = 8 * XSTRIDE;                        // +8 cols (a1/a3 rows)

    #pragma unroll
    for (int kx = 0; kx < 5; ++kx) {
        #pragma unroll
        for (int kh = 0; kh < 2; ++kh) {
            const int o0 = ab0 + kx * XSTRIDE + kh * 8;
            const int o1 = ab1 + kx * XSTRIDE + kh * 8;

            uint32_t p0a0 = xs[o0],      p0a1 = xs[o0 + CB];
            uint32_t p0a2 = xs[o0 + 4],  p0a3 = xs[o0 + CB + 4];
            uint32_t p1a0 = xs[o1],      p1a1 = xs[o1 + CB];
            uint32_t p1a2 = xs[o1 + 4],  p1a3 = xs[o1 + CB + 4];

            uint2 B0 = wsm[((kx * 2 + kh) * 2 + 0) * 32 + t];
            uint2 B1 = wsm[((kx * 2 + kh) * 2 + 1) * 32 + t];

            // 4 independent accumulator chains.
            MMA(d00, p0a0, p0a1, p0a2, p0a3, B0.x, B0.y);
            MMA(d10, p1a0, p1a1, p1a2, p1a3, B0.x, B0.y);
            MMA(d01, p0a0, p0a1, p0a2, p0a3, B1.x, B1.y);
            MMA(d11, p1a0, p1a1, p1a2, p1a3, B1.x, B1.y);
        }
    }

    // Epilogue: D frag m16n8: d[0]:(m,oc0) d[1]:(m,oc0+1) d[2/3]: m+8.
    const int oc0 = 2 * j;
    #pragma unroll
    for (int mt = 0; mt < 2; ++mt) {
        const int q = Q0 + 32 * w + 16 * mt + m;
        float* da = mt ? d10 : d00;
        float* db = mt ? d11 : d01;
        float* o = out + (((size_t)b * 16 + oc0) * 252 + p) * 252 + q;
        o[0] = da[0];  o[8] = da[2];
        o += 252 * 252;
        o[0] = da[1];  o[8] = da[3];
        o = out + (((size_t)b * 16 + 8 + oc0) * 252 + p) * 252 + q;
        o[0] = db[0];  o[8] = db[2];
        o += 252 * 252;
        o[0] = db[1];  o[8] = db[3];
    }
}

extern "C" void kernel_launch(void* const* d_in, const int* in_sizes, int n_in,
                              void* d_out, int out_size)
{
    const float* x  = (const float*)d_in[0];
    const float* w3 = (const float*)d_in[1];
    const float* b3 = (const float*)d_in[2];
    const float* w4 = (const float*)d_in[3];
    const float* b4 = (const float*)d_in[4];
    const float* w6 = (const float*)d_in[5];
    const float* b6 = (const float*)d_in[6];
    float* out = (float*)d_out;

    wfrag_kernel<<<5, 128>>>(w3, w4, w6);
    conv_mma_kernel<<<dim3(2, 252, 128), 128>>>(x, b3, b4, b6, out);
}

// round 15
// speedup vs baseline: 4.3802x; 1.2888x over previous
#include <cuda_runtime.h>
#include <cuda_fp16.h>
#include <cstdint>

// ---------------------------------------------------------------------------
// C3 layer via single-term fp16 tensor-core implicit GEMM (mma.sync).
// R15: smem-wavefront optimization.
//  - xs tap-major [tp][col], plane stride 136 (=8 mod 32):
//      * staging: 4 consecutive cols -> one STS.128, conflict-free
//      * mainloop A LDS.32: banks 8j+m -> conflict-free
//  - epilogue: D-frags -> smem (stride 132, conflict-free) -> coalesced
//      LDS.128 + STG.128.
// ---------------------------------------------------------------------------

__device__ uint2 g_wfrag[5*2*2*32];   // [kx][kh][nh][lane] = (b0, b1)

__device__ constexpr int POC[6][10] = {
    {0, 4, 5, 6,  9, 10, 11, 12, 14, 15},
    {0, 1, 5, 6,  7, 10, 11, 12, 13, 15},
    {0, 1, 2, 6,  7,  8, 11, 13, 14, 15},
    {1, 2, 3, 6,  7,  8,  9, 12, 14, 15},
    {2, 3, 4, 7,  8,  9, 10, 12, 13, 15},
    {3, 4, 5, 8,  9, 10, 11, 13, 14, 15}
};
__device__ constexpr int POFF[6][10] = {
    {  0, 300, 375, 450, 750,  850,  950, 1050, 1250, 1350},
    { 25,  75, 400, 475, 550,  875,  975, 1075, 1150, 1375},
    { 50, 100, 150, 500, 575,  650, 1000, 1175, 1275, 1400},
    {125, 175, 225, 525, 600,  675,  775, 1100, 1300, 1425},
    {200, 250, 325, 625, 700,  800,  900, 1125, 1200, 1450},
    {275, 350, 425, 725, 825,  925, 1025, 1225, 1325, 1475}
};

__device__ __forceinline__ uint32_t packh2(float lo, float hi) {
    __half2 h = __floats2half2_rn(lo, hi);
    uint32_t u;
    asm("mov.b32 %0, %1;" : "=r"(u) : "r"(*(uint32_t*)&h));
    return u;
}

// ---------------- wfrag ----------------
__device__ __forceinline__ float wlookup(const float* w3, const float* w4,
                                         const float* w6, int oc, int tap, int kx)
{
    if (tap >= 30) return 0.0f;
    int c  = tap / 5;
    int ky = tap % 5;
    int base = -1;
    for (int j = 0; j < 10; ++j)
        if (POC[c][j] == oc) { base = POFF[c][j]; break; }
    if (base < 0) return 0.0f;
    int off = base + ky * 5 + kx;
    return (off < 450) ? w3[off] : (off < 1350) ? w4[off - 450] : w6[off - 1350];
}

__global__ void wfrag_kernel(const float* __restrict__ w3,
                             const float* __restrict__ w4,
                             const float* __restrict__ w6)
{
    int idx = blockIdx.x * 128 + threadIdx.x;   // 0..639
    if (idx >= 640) return;
    int t  = idx & 31;
    int nh = (idx >> 5) & 1;
    int kh = (idx >> 6) & 1;
    int kx = idx >> 7;
    int j = t & 3, n = t >> 2;
    int oc = nh * 8 + n;

    float w0 = wlookup(w3, w4, w6, oc, kh*16 + 2*j,     kx);
    float w1 = wlookup(w3, w4, w6, oc, kh*16 + 2*j + 1, kx);
    float w2 = wlookup(w3, w4, w6, oc, kh*16 + 2*j + 8, kx);
    float w3v= wlookup(w3, w4, w6, oc, kh*16 + 2*j + 9, kx);

    uint2 d;
    d.x = packh2(w0, w1);
    d.y = packh2(w2, w3v);
    g_wfrag[idx] = d;
}

// ---------------- conv ----------------
#define MMA(d, a0,a1,a2,a3, b0,b1)                                             \
    asm volatile("mma.sync.aligned.m16n8k16.row.col.f32.f16.f16.f32 "          \
                 "{%0,%1,%2,%3}, {%4,%5,%6,%7}, {%8,%9}, {%0,%1,%2,%3};"       \
                 : "+f"(d[0]), "+f"(d[1]), "+f"(d[2]), "+f"(d[3])              \
                 : "r"(a0), "r"(a1), "r"(a2), "r"(a3), "r"(b0), "r"(b1))

#define PST 136   // plane stride (u32) per tap-pair; 136 % 32 == 8

__global__ __launch_bounds__(128) void conv_mma_kernel(
    const float* __restrict__ x,
    const float* __restrict__ b3, const float* __restrict__ b4,
    const float* __restrict__ b6, float* __restrict__ out)
{
    // xs: 16 tap-pair planes x 136 cols (132 used). Reused as fp32
    // epilogue buffer [16 oc][132 q] after the mainloop.
    __shared__ __align__(16) uint32_t xs[16 * PST];
    __shared__ uint2 wsm[640];
    __shared__ float bsm[16];

    const int tid = threadIdx.x;
    const int b = blockIdx.z, p = blockIdx.y;
    const int Q0 = blockIdx.x ? 124 : 0;

    for (int i = tid; i < 640; i += 128) wsm[i] = g_wfrag[i];
    if (tid < 16)
        bsm[tid] = (tid < 6) ? b3[tid] : (tid < 15) ? b4[tid - 6] : b6[0];
    // Zero plane 15 (taps 30,31 padding).
    for (int i = tid; i < PST; i += 128)
        xs[15 * PST + i] = 0;

    // Stage: i=(tap-pair tp, 4-col segment seg). Two coalesced float4 row
    // loads -> 4 packed u32 (cols contiguous in tap-major layout)
    // -> single STS.128, conflict-free (quad-bank = 34*tp+seg distinct mod 8).
    for (int i = tid; i < 495; i += 128) {
        int tp = i / 33, seg = i % 33;
        int t0 = 2 * tp, t1 = t0 + 1;
        int c0 = t0 / 5, ky0 = t0 % 5;
        int c1 = t1 / 5, ky1 = t1 % 5;
        float4 f0 = *(const float4*)(x + (((size_t)(b * 6 + c0)) * 256 + (p + ky0)) * 256 + Q0 + seg * 4);
        float4 f1 = *(const float4*)(x + (((size_t)(b * 6 + c1)) * 256 + (p + ky1)) * 256 + Q0 + seg * 4);
        uint4 v;
        v.x = packh2(f0.x, f1.x);
        v.y = packh2(f0.y, f1.y);
        v.z = packh2(f0.z, f1.z);
        v.w = packh2(f0.w, f1.w);
        *(uint4*)&xs[tp * PST + seg * 4] = v;
    }
    __syncthreads();

    const int w = tid >> 5, t = tid & 31;
    const int j = t & 3, m = t >> 2;

    float d00[4], d01[4], d10[4], d11[4];
    {
        int oc0 = 2 * j;
        d00[0] = bsm[oc0];     d00[1] = bsm[oc0 + 1];  d00[2] = d00[0]; d00[3] = d00[1];
        d01[0] = bsm[8 + oc0]; d01[1] = bsm[9 + oc0];  d01[2] = d01[0]; d01[3] = d01[1];
        d10[0] = d00[0]; d10[1] = d00[1]; d10[2] = d00[0]; d10[3] = d00[1];
        d11[0] = d01[0]; d11[1] = d01[1]; d11[2] = d01[0]; d11[3] = d01[1];
    }

    const int cb = 32 * w + m;      // m-tile 0 column for this lane

    #pragma unroll
    for (int kx = 0; kx < 5; ++kx) {
        #pragma unroll
        for (int kh = 0; kh < 2; ++kh) {
            const int plo = (kh * 8 + j) * PST + cb + kx;         // a0 plane
            const int phi = (kh * 8 + j + 4) * PST + cb + kx;     // a2 plane

            uint32_t p0a0 = xs[plo],      p0a1 = xs[plo + 8];
            uint32_t p0a2 = xs[phi],      p0a3 = xs[phi + 8];
            uint32_t p1a0 = xs[plo + 16], p1a1 = xs[plo + 24];
            uint32_t p1a2 = xs[phi + 16], p1a3 = xs[phi + 24];

            uint2 B0 = wsm[((kx * 2 + kh) * 2 + 0) * 32 + t];
            uint2 B1 = wsm[((kx * 2 + kh) * 2 + 1) * 32 + t];

            MMA(d00, p0a0, p0a1, p0a2, p0a3, B0.x, B0.y);
            MMA(d10, p1a0, p1a1, p1a2, p1a3, B0.x, B0.y);
            MMA(d01, p0a0, p0a1, p0a2, p0a3, B1.x, B1.y);
            MMA(d11, p1a0, p1a1, p1a2, p1a3, B1.x, B1.y);
        }
    }

    // ---- Epilogue: transpose via smem, then coalesced STG.128 ----
    __syncthreads();            // xs reads done; safe to overwrite
    float* ep = (float*)xs;     // [16 oc][132 q], stride 132 (banks 8j+m: cf)
    {
        const int oc0 = 2 * j;
        const int q0l = 32 * w + m;
        ep[(oc0    ) * 132 + q0l]      = d00[0];
        ep[(oc0 + 1) * 132 + q0l]      = d00[1];
        ep[(oc0    ) * 132 + q0l + 8]  = d00[2];
        ep[(oc0 + 1) * 132 + q0l + 8]  = d00[3];
        ep[(oc0 + 8) * 132 + q0l]      = d01[0];
        ep[(oc0 + 9) * 132 + q0l]      = d01[1];
        ep[(oc0 + 8) * 132 + q0l + 8]  = d01[2];
        ep[(oc0 + 9) * 132 + q0l + 8]  = d01[3];
        const int q1l = q0l + 16;
        ep[(oc0    ) * 132 + q1l]      = d10[0];
        ep[(oc0 + 1) * 132 + q1l]      = d10[1];
        ep[(oc0    ) * 132 + q1l + 8]  = d10[2];
        ep[(oc0 + 1) * 132 + q1l + 8]  = d10[3];
        ep[(oc0 + 8) * 132 + q1l]      = d11[0];
        ep[(oc0 + 9) * 132 + q1l]      = d11[1];
        ep[(oc0 + 8) * 132 + q1l + 8]  = d11[2];
        ep[(oc0 + 9) * 132 + q1l + 8]  = d11[3];
    }
    __syncthreads();

    // 16 oc x 128 q floats = 512 float4; 4 per thread, fully coalesced.
    #pragma unroll
    for (int k = 0; k < 4; ++k) {
        int i = tid + k * 128;
        int oc = i >> 5, v = i & 31;
        float4 r = *(const float4*)&ep[oc * 132 + 4 * v];
        *(float4*)(out + (((size_t)b * 16 + oc) * 252 + p) * 252 + Q0 + 4 * v) = r;
    }
}

extern "C" void kernel_launch(void* const* d_in, const int* in_sizes, int n_in,
                              void* d_out, int out_size)
{
    const float* x  = (const float*)d_in[0];
    const float* w3 = (const float*)d_in[1];
    const float* b3 = (const float*)d_in[2];
    const float* w4 = (const float*)d_in[3];
    const float* b4 = (const float*)d_in[4];
    const float* w6 = (const float*)d_in[5];
    const float* b6 = (const float*)d_in[6];
    float* out = (float*)d_out;

    wfrag_kernel<<<5, 128>>>(w3, w4, w6);
    conv_mma_kernel<<<dim3(2, 252, 128), 128>>>(x, b3, b4, b6, out);
}

// round 16
// speedup vs baseline: 4.3923x; 1.0028x over previous
#include <cuda_runtime.h>
#include <cuda_fp16.h>
#include <cstdint>

// ---------------------------------------------------------------------------
// C3 layer via single-term fp16 tensor-core implicit GEMM (mma.sync).
// R15: smem-wavefront optimization.
//  - xs tap-major [tp][col], plane stride 136 (=8 mod 32):
//      * staging: 4 consecutive cols -> one STS.128, conflict-free
//      * mainloop A LDS.32: banks 8j+m -> conflict-free
//  - epilogue: D-frags -> smem (stride 132, conflict-free) -> coalesced
//      LDS.128 + STG.128.
// ---------------------------------------------------------------------------

__device__ uint2 g_wfrag[5*2*2*32];   // [kx][kh][nh][lane] = (b0, b1)

__device__ constexpr int POC[6][10] = {
    {0, 4, 5, 6,  9, 10, 11, 12, 14, 15},
    {0, 1, 5, 6,  7, 10, 11, 12, 13, 15},
    {0, 1, 2, 6,  7,  8, 11, 13, 14, 15},
    {1, 2, 3, 6,  7,  8,  9, 12, 14, 15},
    {2, 3, 4, 7,  8,  9, 10, 12, 13, 15},
    {3, 4, 5, 8,  9, 10, 11, 13, 14, 15}
};
__device__ constexpr int POFF[6][10] = {
    {  0, 300, 375, 450, 750,  850,  950, 1050, 1250, 1350},
    { 25,  75, 400, 475, 550,  875,  975, 1075, 1150, 1375},
    { 50, 100, 150, 500, 575,  650, 1000, 1175, 1275, 1400},
    {125, 175, 225, 525, 600,  675,  775, 1100, 1300, 1425},
    {200, 250, 325, 625, 700,  800,  900, 1125, 1200, 1450},
    {275, 350, 425, 725, 825,  925, 1025, 1225, 1325, 1475}
};

__device__ __forceinline__ uint32_t packh2(float lo, float hi) {
    __half2 h = __floats2half2_rn(lo, hi);
    uint32_t u;
    asm("mov.b32 %0, %1;" : "=r"(u) : "r"(*(uint32_t*)&h));
    return u;
}

// ---------------- wfrag ----------------
__device__ __forceinline__ float wlookup(const float* w3, const float* w4,
                                         const float* w6, int oc, int tap, int kx)
{
    if (tap >= 30) return 0.0f;
    int c  = tap / 5;
    int ky = tap % 5;
    int base = -1;
    for (int j = 0; j < 10; ++j)
        if (POC[c][j] == oc) { base = POFF[c][j]; break; }
    if (base < 0) return 0.0f;
    int off = base + ky * 5 + kx;
    return (off < 450) ? w3[off] : (off < 1350) ? w4[off - 450] : w6[off - 1350];
}

__global__ void wfrag_kernel(const float* __restrict__ w3,
                             const float* __restrict__ w4,
                             const float* __restrict__ w6)
{
    int idx = blockIdx.x * 128 + threadIdx.x;   // 0..639
    if (idx >= 640) return;
    int t  = idx & 31;
    int nh = (idx >> 5) & 1;
    int kh = (idx >> 6) & 1;
    int kx = idx >> 7;
    int j = t & 3, n = t >> 2;
    int oc = nh * 8 + n;

    float w0 = wlookup(w3, w4, w6, oc, kh*16 + 2*j,     kx);
    float w1 = wlookup(w3, w4, w6, oc, kh*16 + 2*j + 1, kx);
    float w2 = wlookup(w3, w4, w6, oc, kh*16 + 2*j + 8, kx);
    float w3v= wlookup(w3, w4, w6, oc, kh*16 + 2*j + 9, kx);

    uint2 d;
    d.x = packh2(w0, w1);
    d.y = packh2(w2, w3v);
    g_wfrag[idx] = d;
}

// ---------------- conv ----------------
#define MMA(d, a0,a1,a2,a3, b0,b1)                                             \
    asm volatile("mma.sync.aligned.m16n8k16.row.col.f32.f16.f16.f32 "          \
                 "{%0,%1,%2,%3}, {%4,%5,%6,%7}, {%8,%9}, {%0,%1,%2,%3};"       \
                 : "+f"(d[0]), "+f"(d[1]), "+f"(d[2]), "+f"(d[3])              \
                 : "r"(a0), "r"(a1), "r"(a2), "r"(a3), "r"(b0), "r"(b1))

#define PST 136   // plane stride (u32) per tap-pair; 136 % 32 == 8

__global__ __launch_bounds__(128) void conv_mma_kernel(
    const float* __restrict__ x,
    const float* __restrict__ b3, const float* __restrict__ b4,
    const float* __restrict__ b6, float* __restrict__ out)
{
    // xs: 16 tap-pair planes x 136 cols (132 used). Reused as fp32
    // epilogue buffer [16 oc][132 q] after the mainloop.
    __shared__ __align__(16) uint32_t xs[16 * PST];
    __shared__ uint2 wsm[640];
    __shared__ float bsm[16];

    const int tid = threadIdx.x;
    const int b = blockIdx.z, p = blockIdx.y;
    const int Q0 = blockIdx.x ? 124 : 0;

    for (int i = tid; i < 640; i += 128) wsm[i] = g_wfrag[i];
    if (tid < 16)
        bsm[tid] = (tid < 6) ? b3[tid] : (tid < 15) ? b4[tid - 6] : b6[0];
    // Zero plane 15 (taps 30,31 padding).
    for (int i = tid; i < PST; i += 128)
        xs[15 * PST + i] = 0;

    // Stage: i=(tap-pair tp, 4-col segment seg). Two coalesced float4 row
    // loads -> 4 packed u32 (cols contiguous in tap-major layout)
    // -> single STS.128, conflict-free (quad-bank = 34*tp+seg distinct mod 8).
    for (int i = tid; i < 495; i += 128) {
        int tp = i / 33, seg = i % 33;
        int t0 = 2 * tp, t1 = t0 + 1;
        int c0 = t0 / 5, ky0 = t0 % 5;
        int c1 = t1 / 5, ky1 = t1 % 5;
        float4 f0 = *(const float4*)(x + (((size_t)(b * 6 + c0)) * 256 + (p + ky0)) * 256 + Q0 + seg * 4);
        float4 f1 = *(const float4*)(x + (((size_t)(b * 6 + c1)) * 256 + (p + ky1)) * 256 + Q0 + seg * 4);
        uint4 v;
        v.x = packh2(f0.x, f1.x);
        v.y = packh2(f0.y, f1.y);
        v.z = packh2(f0.z, f1.z);
        v.w = packh2(f0.w, f1.w);
        *(uint4*)&xs[tp * PST + seg * 4] = v;
    }
    __syncthreads();

    const int w = tid >> 5, t = tid & 31;
    const int j = t & 3, m = t >> 2;

    float d00[4], d01[4], d10[4], d11[4];
    {
        int oc0 = 2 * j;
        d00[0] = bsm[oc0];     d00[1] = bsm[oc0 + 1];  d00[2] = d00[0]; d00[3] = d00[1];
        d01[0] = bsm[8 + oc0]; d01[1] = bsm[9 + oc0];  d01[2] = d01[0]; d01[3] = d01[1];
        d10[0] = d00[0]; d10[1] = d00[1]; d10[2] = d00[0]; d10[3] = d00[1];
        d11[0] = d01[0]; d11[1] = d01[1]; d11[2] = d01[0]; d11[3] = d01[1];
    }

    const int cb = 32 * w + m;      // m-tile 0 column for this lane

    #pragma unroll
    for (int kx = 0; kx < 5; ++kx) {
        #pragma unroll
        for (int kh = 0; kh < 2; ++kh) {
            const int plo = (kh * 8 + j) * PST + cb + kx;         // a0 plane
            const int phi = (kh * 8 + j + 4) * PST + cb + kx;     // a2 plane

            uint32_t p0a0 = xs[plo],      p0a1 = xs[plo + 8];
            uint32_t p0a2 = xs[phi],      p0a3 = xs[phi + 8];
            uint32_t p1a0 = xs[plo + 16], p1a1 = xs[plo + 24];
            uint32_t p1a2 = xs[phi + 16], p1a3 = xs[phi + 24];

            uint2 B0 = wsm[((kx * 2 + kh) * 2 + 0) * 32 + t];
            uint2 B1 = wsm[((kx * 2 + kh) * 2 + 1) * 32 + t];

            MMA(d00, p0a0, p0a1, p0a2, p0a3, B0.x, B0.y);
            MMA(d10, p1a0, p1a1, p1a2, p1a3, B0.x, B0.y);
            MMA(d01, p0a0, p0a1, p0a2, p0a3, B1.x, B1.y);
            MMA(d11, p1a0, p1a1, p1a2, p1a3, B1.x, B1.y);
        }
    }

    // ---- Epilogue: transpose via smem, then coalesced STG.128 ----
    __syncthreads();            // xs reads done; safe to overwrite
    float* ep = (float*)xs;     // [16 oc][132 q], stride 132 (banks 8j+m: cf)
    {
        const int oc0 = 2 * j;
        const int q0l = 32 * w + m;
        ep[(oc0    ) * 132 + q0l]      = d00[0];
        ep[(oc0 + 1) * 132 + q0l]      = d00[1];
        ep[(oc0    ) * 132 + q0l + 8]  = d00[2];
        ep[(oc0 + 1) * 132 + q0l + 8]  = d00[3];
        ep[(oc0 + 8) * 132 + q0l]      = d01[0];
        ep[(oc0 + 9) * 132 + q0l]      = d01[1];
        ep[(oc0 + 8) * 132 + q0l + 8]  = d01[2];
        ep[(oc0 + 9) * 132 + q0l + 8]  = d01[3];
        const int q1l = q0l + 16;
        ep[(oc0    ) * 132 + q1l]      = d10[0];
        ep[(oc0 + 1) * 132 + q1l]      = d10[1];
        ep[(oc0    ) * 132 + q1l + 8]  = d10[2];
        ep[(oc0 + 1) * 132 + q1l + 8]  = d10[3];
        ep[(oc0 + 8) * 132 + q1l]      = d11[0];
        ep[(oc0 + 9) * 132 + q1l]      = d11[1];
        ep[(oc0 + 8) * 132 + q1l + 8]  = d11[2];
        ep[(oc0 + 9) * 132 + q1l + 8]  = d11[3];
    }
    __syncthreads();

    // 16 oc x 128 q floats = 512 float4; 4 per thread, fully coalesced.
    #pragma unroll
    for (int k = 0; k < 4; ++k) {
        int i = tid + k * 128;
        int oc = i >> 5, v = i & 31;
        float4 r = *(const float4*)&ep[oc * 132 + 4 * v];
        *(float4*)(out + (((size_t)b * 16 + oc) * 252 + p) * 252 + Q0 + 4 * v) = r;
    }
}

extern "C" void kernel_launch(void* const* d_in, const int* in_sizes, int n_in,
                              void* d_out, int out_size)
{
    const float* x  = (const float*)d_in[0];
    const float* w3 = (const float*)d_in[1];
    const float* b3 = (const float*)d_in[2];
    const float* w4 = (const float*)d_in[3];
    const float* b4 = (const float*)d_in[4];
    const float* w6 = (const float*)d_in[5];
    const float* b6 = (const float*)d_in[6];
    float* out = (float*)d_out;

    wfrag_kernel<<<5, 128>>>(w3, w4, w6);
    conv_mma_kernel<<<dim3(2, 252, 128), 128>>>(x, b3, b4, b6, out);
}

// round 17
// speedup vs baseline: 5.3573x; 1.2197x over previous
#include <cuda_runtime.h>
#include <cuda_fp16.h>
#include <cstdint>

// ---------------------------------------------------------------------------
// C3 layer via single-term fp16 tensor-core implicit GEMM (mma.sync).
// R17: one 256-thread CTA per (batch, output row): 8 warps x 32 px = 256 px
// (252 valid). Halves per-CTA fixed wavefront costs vs two 128-thread CTAs.
//  - xs tap-major [tp][col], plane stride 264 (=8 mod 32): staging STS.128
//    conflict-free, mainloop A LDS.32 banks 8j+m conflict-free.
//  - weights: one LDS.128 (uint4 = B0|B1) per chunk.
//  - epilogue via smem (stride 260, conflict-free) -> coalesced STG.128.
// ---------------------------------------------------------------------------

__device__ uint2 g_wfrag[5*2*2*32];   // [kx][kh][nh][lane] = (b0, b1)

__device__ constexpr int POC[6][10] = {
    {0, 4, 5, 6,  9, 10, 11, 12, 14, 15},
    {0, 1, 5, 6,  7, 10, 11, 12, 13, 15},
    {0, 1, 2, 6,  7,  8, 11, 13, 14, 15},
    {1, 2, 3, 6,  7,  8,  9, 12, 14, 15},
    {2, 3, 4, 7,  8,  9, 10, 12, 13, 15},
    {3, 4, 5, 8,  9, 10, 11, 13, 14, 15}
};
__device__ constexpr int POFF[6][10] = {
    {  0, 300, 375, 450, 750,  850,  950, 1050, 1250, 1350},
    { 25,  75, 400, 475, 550,  875,  975, 1075, 1150, 1375},
    { 50, 100, 150, 500, 575,  650, 1000, 1175, 1275, 1400},
    {125, 175, 225, 525, 600,  675,  775, 1100, 1300, 1425},
    {200, 250, 325, 625, 700,  800,  900, 1125, 1200, 1450},
    {275, 350, 425, 725, 825,  925, 1025, 1225, 1325, 1475}
};

__device__ __forceinline__ uint32_t packh2(float lo, float hi) {
    __half2 h = __floats2half2_rn(lo, hi);
    uint32_t u;
    asm("mov.b32 %0, %1;" : "=r"(u) : "r"(*(uint32_t*)&h));
    return u;
}

// ---------------- wfrag ----------------
__device__ __forceinline__ float wlookup(const float* w3, const float* w4,
                                         const float* w6, int oc, int tap, int kx)
{
    if (tap >= 30) return 0.0f;
    int c  = tap / 5;
    int ky = tap % 5;
    int base = -1;
    for (int j = 0; j < 10; ++j)
        if (POC[c][j] == oc) { base = POFF[c][j]; break; }
    if (base < 0) return 0.0f;
    int off = base + ky * 5 + kx;
    return (off < 450) ? w3[off] : (off < 1350) ? w4[off - 450] : w6[off - 1350];
}

__global__ void wfrag_kernel(const float* __restrict__ w3,
                             const float* __restrict__ w4,
                             const float* __restrict__ w6)
{
    int idx = blockIdx.x * 128 + threadIdx.x;   // 0..639
    if (idx >= 640) return;
    int t  = idx & 31;
    int nh = (idx >> 5) & 1;
    int kh = (idx >> 6) & 1;
    int kx = idx >> 7;
    int j = t & 3, n = t >> 2;
    int oc = nh * 8 + n;

    float w0 = wlookup(w3, w4, w6, oc, kh*16 + 2*j,     kx);
    float w1 = wlookup(w3, w4, w6, oc, kh*16 + 2*j + 1, kx);
    float w2 = wlookup(w3, w4, w6, oc, kh*16 + 2*j + 8, kx);
    float w3v= wlookup(w3, w4, w6, oc, kh*16 + 2*j + 9, kx);

    uint2 d;
    d.x = packh2(w0, w1);
    d.y = packh2(w2, w3v);
    g_wfrag[idx] = d;
}

// ---------------- conv ----------------
#define MMA(d, a0,a1,a2,a3, b0,b1)                                             \
    asm volatile("mma.sync.aligned.m16n8k16.row.col.f32.f16.f16.f32 "          \
                 "{%0,%1,%2,%3}, {%4,%5,%6,%7}, {%8,%9}, {%0,%1,%2,%3};"       \
                 : "+f"(d[0]), "+f"(d[1]), "+f"(d[2]), "+f"(d[3])              \
                 : "r"(a0), "r"(a1), "r"(a2), "r"(a3), "r"(b0), "r"(b1))

#define PST 264   // plane stride (u32); 264 % 32 == 8

__global__ __launch_bounds__(256) void conv_mma_kernel(
    const float* __restrict__ x,
    const float* __restrict__ b3, const float* __restrict__ b4,
    const float* __restrict__ b6, float* __restrict__ out)
{
    // xs: 16 tap-pair planes x 264 cols (256 staged + 8 zero pad).
    // Reused as fp32 epilogue buffer [16 oc][260] after the mainloop.
    __shared__ __align__(16) uint32_t xs[16 * PST];
    __shared__ __align__(16) uint4 wsm[320];    // [chunk 0..9][lane] = B0|B1
    __shared__ float bsm[16];

    const int tid = threadIdx.x;
    const int b = blockIdx.z, p = blockIdx.y;

    // Merge the two nh-halves of g_wfrag into uint4 entries.
    for (int i = tid; i < 320; i += 256) {
        int ch = i >> 5, t = i & 31;
        uint2 lo = g_wfrag[(ch * 2    ) * 32 + t];
        uint2 hi = g_wfrag[(ch * 2 + 1) * 32 + t];
        wsm[i] = make_uint4(lo.x, lo.y, hi.x, hi.y);
    }
    if (tid < 16)
        bsm[tid] = (tid < 6) ? b3[tid] : (tid < 15) ? b4[tid - 6] : b6[0];
    // Zero plane 15 (tap padding) and the 8 pad cols of every plane.
    for (int i = tid; i < PST; i += 256)
        xs[15 * PST + i] = 0;
    if (tid < 128) {
        int tp = tid >> 3, c = tid & 7;
        xs[tp * PST + 256 + c] = 0;
    }

    // Stage: i = (tap-pair tp, 4-col segment seg in 0..63). Two coalesced
    // float4 row loads -> 4 packed u32 -> one STS.128 (conflict-free).
    for (int i = tid; i < 960; i += 256) {
        int tp = i >> 6, seg = i & 63;
        int t0 = 2 * tp, t1 = t0 + 1;
        int c0 = t0 / 5, ky0 = t0 % 5;
        int c1 = t1 / 5, ky1 = t1 % 5;
        float4 f0 = *(const float4*)(x + (((size_t)(b * 6 + c0)) * 256 + (p + ky0)) * 256 + seg * 4);
        float4 f1 = *(const float4*)(x + (((size_t)(b * 6 + c1)) * 256 + (p + ky1)) * 256 + seg * 4);
        uint4 v;
        v.x = packh2(f0.x, f1.x);
        v.y = packh2(f0.y, f1.y);
        v.z = packh2(f0.z, f1.z);
        v.w = packh2(f0.w, f1.w);
        *(uint4*)&xs[tp * PST + seg * 4] = v;
    }
    __syncthreads();

    const int w = tid >> 5, t = tid & 31;
    const int j = t & 3, m = t >> 2;

    float d00[4], d01[4], d10[4], d11[4];
    {
        int oc0 = 2 * j;
        d00[0] = bsm[oc0];     d00[1] = bsm[oc0 + 1];  d00[2] = d00[0]; d00[3] = d00[1];
        d01[0] = bsm[8 + oc0]; d01[1] = bsm[9 + oc0];  d01[2] = d01[0]; d01[3] = d01[1];
        d10[0] = d00[0]; d10[1] = d00[1]; d10[2] = d00[0]; d10[3] = d00[1];
        d11[0] = d01[0]; d11[1] = d01[1]; d11[2] = d01[0]; d11[3] = d01[1];
    }

    const int cb = 32 * w + m;      // m-tile 0 column for this lane

    #pragma unroll
    for (int kx = 0; kx < 5; ++kx) {
        #pragma unroll
        for (int kh = 0; kh < 2; ++kh) {
            const int plo = (kh * 8 + j) * PST + cb + kx;
            const int phi = (kh * 8 + j + 4) * PST + cb + kx;

            uint32_t p0a0 = xs[plo],      p0a1 = xs[plo + 8];
            uint32_t p0a2 = xs[phi],      p0a3 = xs[phi + 8];
            uint32_t p1a0 = xs[plo + 16], p1a1 = xs[plo + 24];
            uint32_t p1a2 = xs[phi + 16], p1a3 = xs[phi + 24];

            uint4 B = wsm[(kx * 2 + kh) * 32 + t];

            MMA(d00, p0a0, p0a1, p0a2, p0a3, B.x, B.y);
            MMA(d10, p1a0, p1a1, p1a2, p1a3, B.x, B.y);
            MMA(d01, p0a0, p0a1, p0a2, p0a3, B.z, B.w);
            MMA(d11, p1a0, p1a1, p1a2, p1a3, B.z, B.w);
        }
    }

    // ---- Epilogue: transpose via smem (stride 260), coalesced STG ----
    __syncthreads();
    float* ep = (float*)xs;     // [16 oc][260]
    {
        const int oc0 = 2 * j;
        const int q0l = 32 * w + m;
        ep[(oc0    ) * 260 + q0l]      = d00[0];
        ep[(oc0 + 1) * 260 + q0l]      = d00[1];
        ep[(oc0    ) * 260 + q0l + 8]  = d00[2];
        ep[(oc0 + 1) * 260 + q0l + 8]  = d00[3];
        ep[(oc0 + 8) * 260 + q0l]      = d01[0];
        ep[(oc0 + 9) * 260 + q0l]      = d01[1];
        ep[(oc0 + 8) * 260 + q0l + 8]  = d01[2];
        ep[(oc0 + 9) * 260 + q0l + 8]  = d01[3];
        const int q1l = q0l + 16;
        ep[(oc0    ) * 260 + q1l]      = d10[0];
        ep[(oc0 + 1) * 260 + q1l]      = d10[1];
        ep[(oc0    ) * 260 + q1l + 8]  = d10[2];
        ep[(oc0 + 1) * 260 + q1l + 8]  = d10[3];
        ep[(oc0 + 8) * 260 + q1l]      = d11[0];
        ep[(oc0 + 9) * 260 + q1l]      = d11[1];
        ep[(oc0 + 8) * 260 + q1l + 8]  = d11[2];
        ep[(oc0 + 9) * 260 + q1l + 8]  = d11[3];
    }
    __syncthreads();

    // 16 oc x 252 q = 1008 float4; ~4 per thread, fully coalesced.
    #pragma unroll
    for (int k = 0; k < 4; ++k) {
        int i = tid + k * 256;
        if (i < 1008) {
            int oc = i / 63, v = i % 63;
            float4 r = *(const float4*)&ep[oc * 260 + 4 * v];
            *(float4*)(out + (((size_t)b * 16 + oc) * 252 + p) * 252 + 4 * v) = r;
        }
    }
}

extern "C" void kernel_launch(void* const* d_in, const int* in_sizes, int n_in,
                              void* d_out, int out_size)
{
    const float* x  = (const float*)d_in[0];
    const float* w3 = (const float*)d_in[1];
    const float* b3 = (const float*)d_in[2];
    const float* w4 = (const float*)d_in[3];
    const float* b4 = (const float*)d_in[4];
    const float* w6 = (const float*)d_in[5];
    const float* b6 = (const float*)d_in[6];
    float* out = (float*)d_out;

    wfrag_kernel<<<5, 128>>>(w3, w4, w6);
    conv_mma_kernel<<<dim3(1, 252, 128), 256>>>(x, b3, b4, b6, out);
}